// round 6
// baseline (speedup 1.0000x reference)
#include <cuda_runtime.h>
#include <cstdint>

// Correlation: out[n,q,y,x] = (1/C) * sum_c d1[n,c,y,x] * d2pad[n,c,y+dy,x+dx]
// q = (dy+4)*9 + (dx+4). Shapes: N=8, C=256, H=96, W=160. Out (8,81,96,160) f32.
//
// R4: 8 px/thread + packed fma.rn.f32x2 + hoisted copy addressing.
// 192-thread blocks = 3 dy-subsets x 64 threads (4 x-groups x 16 rows).

#define CC   256
#define HH   96
#define WW   160
#define NN   8

constexpr int TX   = 32;   // tile width in pixels
constexpr int TTY  = 16;   // tile rows
constexpr int KC   = 8;    // channels per smem chunk
constexpr int S1S  = 36;   // s1 row stride (floats), 32 used
constexpr int S2S  = 44;   // s2 row stride (floats), 40 used
constexpr int S2R  = 18;   // s2 rows (16 + 2)
constexpr int NT   = 192;
constexpr int NCH  = CC / KC;
constexpr int S1_F = KC * TTY * S1S;        // 4608
constexpr int S2_F = KC * S2R * S2S;        // 6336
constexpr int STAGE_F = S1_F + S2_F;        // 10944
constexpr int SMEM_BYTES = 2 * STAGE_F * 4; // 87552

__device__ __forceinline__ void cp16(uint32_t dst, const void* src, bool p) {
    asm volatile("cp.async.cg.shared.global [%0], [%1], 16, %2;\n"
                 :: "r"(dst), "l"(src), "r"(p ? 16 : 0));
}
__device__ __forceinline__ void cp_commit() {
    asm volatile("cp.async.commit_group;\n" ::: "memory");
}
template <int N>
__device__ __forceinline__ void cp_wait() {
    asm volatile("cp.async.wait_group %0;\n" :: "n"(N) : "memory");
}
__device__ __forceinline__ unsigned long long pk(float lo, float hi) {
    unsigned long long r;
    asm("mov.b64 %0, {%1, %2};" : "=l"(r) : "f"(lo), "f"(hi));
    return r;
}
__device__ __forceinline__ void upk(unsigned long long v, float& lo, float& hi) {
    asm("mov.b64 {%0, %1}, %2;" : "=f"(lo), "=f"(hi) : "l"(v));
}
__device__ __forceinline__ void fma2(unsigned long long& acc,
                                     unsigned long long a,
                                     unsigned long long b) {
    asm("fma.rn.f32x2 %0, %1, %2, %0;" : "+l"(acc) : "l"(a), "l"(b));
}

__global__ __launch_bounds__(NT, 2)
void corr_kernel(const float* __restrict__ d1,
                 const float* __restrict__ d2,
                 float* __restrict__ out)
{
    extern __shared__ float smem[];

    // blockIdx.x = g3 + 3*tile_x ; blockIdx.y = tile_y + 6*n
    const int g3  = blockIdx.x % 3;
    const int tlx = blockIdx.x / 3;
    const int ty0 = (blockIdx.y % 6) * TTY;
    const int n   = blockIdx.y / 6;
    const int x0  = tlx * TX;

    const int t    = threadIdx.x;   // 0..191
    const int tsub = t / 64;        // dy within group (uniform per warp-pair)
    const int tl   = t % 64;
    const int g    = tl % 4;        // x-group of 8 pixels
    const int tyl  = tl / 4;        // 0..15

    unsigned long long acc[9][4];
#pragma unroll
    for (int dxi = 0; dxi < 9; dxi++)
#pragma unroll
        for (int p = 0; p < 4; p++) acc[dxi][p] = 0ull;

    const int dy_base = 3 * g3 - 4;
    const int yb      = ty0 + dy_base;
    const float* d1n = d1 + (size_t)n * CC * HH * WW;
    const float* d2n = d2 + (size_t)n * CC * HH * WW;

    const uint32_t smem_u32 = (uint32_t)__cvta_generic_to_shared(smem);

    // ---- per-thread copy-slot precompute (hoisted out of mainloop) ----
    // d1: threads 0..127 each copy one float4 per channel.
    const bool ok1 = (t < 128);
    const int  yy1 = (t >> 3) & 15;
    const int  xg1 = t & 7;
    const float* src1 = d1n + (size_t)(ty0 + yy1) * WW + x0 + xg1 * 4;
    const uint32_t dst1 = (uint32_t)((yy1 * S1S + xg1 * 4) * 4);
    // d2: threads 0..179 each copy one float4 per channel (zero-padded).
    const bool v2  = (t < 180);
    const int  rr2 = t / 10;
    const int  xg2 = t % 10;
    const int  gy2 = yb + rr2;
    const int  gx2 = x0 - 4 + xg2 * 4;
    const bool ok2 = v2 && gy2 >= 0 && gy2 < HH && gx2 >= 0 && gx2 + 3 < WW;
    const float* src2 = ok2 ? d2n + (size_t)gy2 * WW + gx2 : d2n;
    const uint32_t dst2 = (uint32_t)((rr2 * S2S + xg2 * 4) * 4);

    // running source pointers (advance one channel per cc step)
    const float* s1p = src1;
    const float* s2p = src2;

    auto load_stage = [&](int stage) {
        const uint32_t s1b = smem_u32 + (uint32_t)(stage * STAGE_F * 4) + dst1;
        const uint32_t s2b = smem_u32 + (uint32_t)(stage * STAGE_F * 4)
                             + (uint32_t)(S1_F * 4) + dst2;
#pragma unroll
        for (int cc = 0; cc < KC; cc++) {
            if (ok1) cp16(s1b + (uint32_t)(cc * TTY * S1S * 4), s1p, true);
            if (v2)  cp16(s2b + (uint32_t)(cc * S2R * S2S * 4), s2p, ok2);
            s1p += HH * WW;
            s2p += HH * WW;
        }
        cp_commit();
    };

    // ---- pipeline ----
    load_stage(0);

    int stage = 0;
    for (int it = 0; it < NCH; it++) {
        if (it + 1 < NCH) {
            load_stage(stage ^ 1);
            cp_wait<1>();
        } else {
            cp_wait<0>();
        }
        __syncthreads();

        const float* s1c = smem + stage * STAGE_F;
        const float* s2c = s1c + S1_F;

#pragma unroll
        for (int c = 0; c < KC; c++) {
            const float* arow = &s1c[(c * TTY + tyl) * S1S + g * 8];
            const ulonglong2 aA = *reinterpret_cast<const ulonglong2*>(arow);
            const ulonglong2 aB = *reinterpret_cast<const ulonglong2*>(arow + 4);
            const unsigned long long ap[4] = {aA.x, aA.y, aB.x, aB.y};

            const float* brow = &s2c[(c * S2R + tyl + tsub) * S2S + g * 8];
            const float4 b0 = *reinterpret_cast<const float4*>(brow);
            const float4 b1 = *reinterpret_cast<const float4*>(brow + 4);
            const float4 b2 = *reinterpret_cast<const float4*>(brow + 8);
            const float4 b3 = *reinterpret_cast<const float4*>(brow + 12);
            const float b[16] = {b0.x, b0.y, b0.z, b0.w, b1.x, b1.y, b1.z, b1.w,
                                 b2.x, b2.y, b2.z, b2.w, b3.x, b3.y, b3.z, b3.w};
            unsigned long long bp[15];
#pragma unroll
            for (int i = 0; i < 15; i++) bp[i] = pk(b[i], b[i + 1]);

#pragma unroll
            for (int dxi = 0; dxi < 9; dxi++) {
#pragma unroll
                for (int p = 0; p < 4; p++)
                    fma2(acc[dxi][p], ap[p], bp[2 * p + dxi]);
            }
        }
        __syncthreads();
        stage ^= 1;
    }

    // ---- epilogue ----
    const float inv = 1.0f / (float)CC;
    const int y  = ty0 + tyl;
    const int xo = x0 + g * 8;
    const int dy = dy_base + tsub;
#pragma unroll
    for (int dxi = 0; dxi < 9; dxi++) {
        const int q = (dy + 4) * 9 + dxi;
        float o[8];
#pragma unroll
        for (int p = 0; p < 4; p++) upk(acc[dxi][p], o[2 * p], o[2 * p + 1]);
        float* op = out + (((size_t)n * 81 + q) * HH + y) * WW + xo;
        *reinterpret_cast<float4*>(op) =
            make_float4(o[0] * inv, o[1] * inv, o[2] * inv, o[3] * inv);
        *reinterpret_cast<float4*>(op + 4) =
            make_float4(o[4] * inv, o[5] * inv, o[6] * inv, o[7] * inv);
    }
}

extern "C" void kernel_launch(void* const* d_in, const int* in_sizes, int n_in,
                              void* d_out, int out_size)
{
    const float* data1 = (const float*)d_in[0];
    const float* data2 = (const float*)d_in[1];
    float* out = (float*)d_out;

    cudaFuncSetAttribute(corr_kernel,
                         cudaFuncAttributeMaxDynamicSharedMemorySize,
                         SMEM_BYTES);

    dim3 grid(3 * (WW / TX), (HH / TTY) * NN, 1);  // (15, 48)
    dim3 block(NT, 1, 1);
    corr_kernel<<<grid, block, SMEM_BYTES>>>(data1, data2, out);
}